// round 2
// baseline (speedup 1.0000x reference)
#include <cuda_runtime.h>
#include <math.h>

#define BB 2
#define SS 2048
#define HH 2048
#define NH 16
#define HD 128
#define MM (BB*SS)   // 4096

// Scratch (device globals — allocation-free rule)
__device__ float g_Q[(size_t)MM*HH];
__device__ float g_K[(size_t)MM*HH];
__device__ float g_V[(size_t)MM*HH];
__device__ float g_A[(size_t)MM*HH];

// ---------------------------------------------------------------------------
// SGEMM: C[M,N] = A[M,K] @ W[K,N] + bias[N]
// 128x128 tile, BK=8, 256 threads, 8x8 per-thread register tile.
// Row/col register groups split as {4*tr .. 4*tr+3} and {64+4*tr ..} so the
// float4 smem reads are stride-1 across the 16-lane groups (conflict-free).
// ---------------------------------------------------------------------------
__global__ __launch_bounds__(256, 2)
void gemm_bias_kernel(const float* __restrict__ A, const float* __restrict__ W,
                      const float* __restrict__ bias, float* __restrict__ C,
                      int M, int N, int K)
{
    __shared__ float As[8][128];   // transposed A tile: As[k][m]
    __shared__ float Bs[8][128];   // Bs[k][n]

    const int tid = threadIdx.x;
    const int tr  = tid >> 4;      // 0..15
    const int tc  = tid & 15;      // 0..15
    const int bm  = blockIdx.y * 128;
    const int bn  = blockIdx.x * 128;

    float acc[8][8];
#pragma unroll
    for (int i = 0; i < 8; i++)
#pragma unroll
        for (int j = 0; j < 8; j++) acc[i][j] = 0.f;

    const float* Ab = A + (size_t)bm * K;
    const float* Wb = W + bn;

    const int a_row = tid >> 1;          // 0..127
    const int a_k4  = (tid & 1) * 4;     // 0 or 4
    const int b_row = tid >> 5;          // 0..7
    const int b_c4  = (tid & 31) * 4;    // 0..124

    for (int kt = 0; kt < K; kt += 8) {
        float4 av = *(const float4*)(Ab + (size_t)a_row * K + kt + a_k4);
        As[a_k4 + 0][a_row] = av.x;
        As[a_k4 + 1][a_row] = av.y;
        As[a_k4 + 2][a_row] = av.z;
        As[a_k4 + 3][a_row] = av.w;
        *(float4*)&Bs[b_row][b_c4] =
            *(const float4*)(Wb + (size_t)(kt + b_row) * N + b_c4);
        __syncthreads();

#pragma unroll
        for (int k = 0; k < 8; k++) {
            float4 a0 = *(const float4*)&As[k][tr * 4];
            float4 a1 = *(const float4*)&As[k][64 + tr * 4];
            float4 b0 = *(const float4*)&Bs[k][tc * 4];
            float4 b1 = *(const float4*)&Bs[k][64 + tc * 4];
            float am[8] = {a0.x, a0.y, a0.z, a0.w, a1.x, a1.y, a1.z, a1.w};
            float wn[8] = {b0.x, b0.y, b0.z, b0.w, b1.x, b1.y, b1.z, b1.w};
#pragma unroll
            for (int i = 0; i < 8; i++)
#pragma unroll
                for (int j = 0; j < 8; j++)
                    acc[i][j] = fmaf(am[i], wn[j], acc[i][j]);
        }
        __syncthreads();
    }

#pragma unroll
    for (int ig = 0; ig < 2; ig++) {
#pragma unroll
        for (int i = 0; i < 4; i++) {
            int row = bm + ig * 64 + tr * 4 + i;
#pragma unroll
            for (int jg = 0; jg < 2; jg++) {
                int col = bn + jg * 64 + tc * 4;
                float4 bb = *(const float4*)(bias + col);
                float4 o;
                o.x = acc[ig * 4 + i][jg * 4 + 0] + bb.x;
                o.y = acc[ig * 4 + i][jg * 4 + 1] + bb.y;
                o.z = acc[ig * 4 + i][jg * 4 + 2] + bb.z;
                o.w = acc[ig * 4 + i][jg * 4 + 3] + bb.w;
                *(float4*)(C + (size_t)row * N + col) = o;
            }
        }
    }
}

// ---------------------------------------------------------------------------
// Flash attention (fp32): per (b, h), 64 query rows per CTA, stream K/V in
// 64-row tiles. Online softmax; row stats replicated in registers across the
// 16 lanes that own each row (no smem races). d=128 fixed.
// smem rows padded to 132 floats (33 float4) -> conflict-free strided float4.
// ---------------------------------------------------------------------------
#define LDQ 132
#define LDP 65
#define ATTN_SMEM_BYTES ((2*64*LDQ + 64*LDP) * (int)sizeof(float))

__global__ __launch_bounds__(256, 2)
void attn_kernel()
{
    extern __shared__ float sm[];
    float* sq  = sm;                 // 64 x LDQ  (Q, pre-scaled)
    float* skv = sm + 64 * LDQ;      // 64 x LDQ  (K then V)
    float* sp  = sm + 2 * 64 * LDQ;  // 64 x LDP  (P = exp(S - m))

    const int tid = threadIdx.x;
    const int tx  = tid & 15;   // key-col group / d-col group
    const int ty  = tid >> 4;   // row group
    const int qt  = blockIdx.x; // query tile (32)
    const int h   = blockIdx.y; // head (16)
    const int b   = blockIdx.z; // batch (2)

    const float scale = rsqrtf((float)HD);

    const float* Qg = g_Q + ((size_t)b * SS + (size_t)qt * 64) * HH + h * HD;
    const float* Kg = g_K + (size_t)b * SS * HH + h * HD;
    const float* Vg = g_V + (size_t)b * SS * HH + h * HD;
    float*       Og = g_A + ((size_t)b * SS + (size_t)qt * 64) * HH + h * HD;

    // Load Q tile (scaled by 1/sqrt(d))
    for (int u = tid; u < 64 * 32; u += 256) {
        int r = u >> 5, c4 = (u & 31) * 4;
        float4 v = *(const float4*)(Qg + (size_t)r * HH + c4);
        v.x *= scale; v.y *= scale; v.z *= scale; v.w *= scale;
        *(float4*)(sq + r * LDQ + c4) = v;
    }

    float4 acc0[4], acc1[4];
#pragma unroll
    for (int i = 0; i < 4; i++) {
        acc0[i] = make_float4(0.f, 0.f, 0.f, 0.f);
        acc1[i] = make_float4(0.f, 0.f, 0.f, 0.f);
    }
    float mrow[4] = {-INFINITY, -INFINITY, -INFINITY, -INFINITY};
    float lrow[4] = {0.f, 0.f, 0.f, 0.f};

    for (int kt = 0; kt < SS; kt += 64) {
        // Load K tile
        for (int u = tid; u < 64 * 32; u += 256) {
            int r = u >> 5, c4 = (u & 31) * 4;
            *(float4*)(skv + r * LDQ + c4) =
                *(const float4*)(Kg + (size_t)(kt + r) * HH + c4);
        }
        __syncthreads();   // covers Q load on first iter too

        // Scores: s[i][j] = q(4ty+i) . k(4tx+j)   (q pre-scaled)
        float s[4][4];
#pragma unroll
        for (int i = 0; i < 4; i++)
#pragma unroll
            for (int j = 0; j < 4; j++) s[i][j] = 0.f;

#pragma unroll 8
        for (int d4 = 0; d4 < 32; d4++) {
            float4 qv[4], kv[4];
#pragma unroll
            for (int i = 0; i < 4; i++)
                qv[i] = *(const float4*)(sq + (4 * ty + i) * LDQ + d4 * 4);
#pragma unroll
            for (int j = 0; j < 4; j++)
                kv[j] = *(const float4*)(skv + (4 * tx + j) * LDQ + d4 * 4);
#pragma unroll
            for (int i = 0; i < 4; i++)
#pragma unroll
                for (int j = 0; j < 4; j++) {
                    s[i][j] = fmaf(qv[i].x, kv[j].x, s[i][j]);
                    s[i][j] = fmaf(qv[i].y, kv[j].y, s[i][j]);
                    s[i][j] = fmaf(qv[i].z, kv[j].z, s[i][j]);
                    s[i][j] = fmaf(qv[i].w, kv[j].w, s[i][j]);
                }
        }

        // Online softmax row update (replicated across the 16 tx lanes)
        float alpha[4];
#pragma unroll
        for (int i = 0; i < 4; i++) {
            float mx = fmaxf(fmaxf(s[i][0], s[i][1]), fmaxf(s[i][2], s[i][3]));
#pragma unroll
            for (int off = 8; off > 0; off >>= 1)
                mx = fmaxf(mx, __shfl_xor_sync(0xffffffffu, mx, off, 16));
            float mn = fmaxf(mrow[i], mx);
            float rs = 0.f;
#pragma unroll
            for (int j = 0; j < 4; j++) {
                float p = __expf(s[i][j] - mn);
                sp[(4 * ty + i) * LDP + 4 * tx + j] = p;
                rs += p;
            }
#pragma unroll
            for (int off = 8; off > 0; off >>= 1)
                rs += __shfl_xor_sync(0xffffffffu, rs, off, 16);
            alpha[i] = __expf(mrow[i] - mn);
            lrow[i]  = alpha[i] * lrow[i] + rs;
            mrow[i]  = mn;
        }
        __syncthreads();   // P written, done reading K

        // Load V tile into skv
        for (int u = tid; u < 64 * 32; u += 256) {
            int r = u >> 5, c4 = (u & 31) * 4;
            *(float4*)(skv + r * LDQ + c4) =
                *(const float4*)(Vg + (size_t)(kt + r) * HH + c4);
        }
        __syncthreads();

        // Rescale accumulator + P@V
#pragma unroll
        for (int i = 0; i < 4; i++) {
            float a = alpha[i];
            acc0[i].x *= a; acc0[i].y *= a; acc0[i].z *= a; acc0[i].w *= a;
            acc1[i].x *= a; acc1[i].y *= a; acc1[i].z *= a; acc1[i].w *= a;
        }
#pragma unroll 4
        for (int j = 0; j < 64; j++) {
            float4 v0 = *(const float4*)(skv + j * LDQ + tx * 4);
            float4 v1 = *(const float4*)(skv + j * LDQ + 64 + tx * 4);
#pragma unroll
            for (int i = 0; i < 4; i++) {
                float p = sp[(4 * ty + i) * LDP + j];
                acc0[i].x = fmaf(p, v0.x, acc0[i].x);
                acc0[i].y = fmaf(p, v0.y, acc0[i].y);
                acc0[i].z = fmaf(p, v0.z, acc0[i].z);
                acc0[i].w = fmaf(p, v0.w, acc0[i].w);
                acc1[i].x = fmaf(p, v1.x, acc1[i].x);
                acc1[i].y = fmaf(p, v1.y, acc1[i].y);
                acc1[i].z = fmaf(p, v1.z, acc1[i].z);
                acc1[i].w = fmaf(p, v1.w, acc1[i].w);
            }
        }
        __syncthreads();   // done reading P / V before next tile overwrites
    }

    // Epilogue: O = acc / l
#pragma unroll
    for (int i = 0; i < 4; i++) {
        float inv = 1.f / lrow[i];
        float4 o0 = acc0[i], o1 = acc1[i];
        o0.x *= inv; o0.y *= inv; o0.z *= inv; o0.w *= inv;
        o1.x *= inv; o1.y *= inv; o1.z *= inv; o1.w *= inv;
        *(float4*)(Og + (size_t)(4 * ty + i) * HH + tx * 4)      = o0;
        *(float4*)(Og + (size_t)(4 * ty + i) * HH + 64 + tx * 4) = o1;
    }
}

// ---------------------------------------------------------------------------
extern "C" void kernel_launch(void* const* d_in, const int* in_sizes, int n_in,
                              void* d_out, int out_size)
{
    const float* X  = (const float*)d_in[0];
    const float* Wq = (const float*)d_in[1];
    const float* bq = (const float*)d_in[2];
    const float* Wk = (const float*)d_in[3];
    const float* bk = (const float*)d_in[4];
    const float* Wv = (const float*)d_in[5];
    const float* bv = (const float*)d_in[6];
    const float* Wo = (const float*)d_in[7];
    const float* bo = (const float*)d_in[8];
    float* out = (float*)d_out;

    float* dQ; cudaGetSymbolAddress((void**)&dQ, g_Q);
    float* dK; cudaGetSymbolAddress((void**)&dK, g_K);
    float* dV; cudaGetSymbolAddress((void**)&dV, g_V);
    float* dA; cudaGetSymbolAddress((void**)&dA, g_A);

    cudaFuncSetAttribute(attn_kernel,
                         cudaFuncAttributeMaxDynamicSharedMemorySize,
                         ATTN_SMEM_BYTES);

    dim3 ggrid(HH / 128, MM / 128);
    gemm_bias_kernel<<<ggrid, 256>>>(X, Wq, bq, dQ, MM, HH, HH);
    gemm_bias_kernel<<<ggrid, 256>>>(X, Wk, bk, dK, MM, HH, HH);
    gemm_bias_kernel<<<ggrid, 256>>>(X, Wv, bv, dV, MM, HH, HH);

    dim3 agrid(SS / 64, NH, BB);
    attn_kernel<<<agrid, 256, ATTN_SMEM_BYTES>>>();

    gemm_bias_kernel<<<ggrid, 256>>>(dA, Wo, bo, out, MM, HH, HH);
}